// round 3
// baseline (speedup 1.0000x reference)
#include <cuda_runtime.h>
#include <math.h>

// ---------------- problem constants ----------------
#define BDIM   4
#define NTOK   3137        // 1 + 56*56
#define DMODEL 768
#define NH     8
#define HD     96
#define HW     56
#define QLEN   3137
#define KHW    28
#define KLEN   785         // 1 + 28*28
#define BH     32          // BDIM*NH
#define MROWS  12548       // BDIM*NTOK
#define SCALE_F 0.10206207261596575f   // 96^-0.5

// ---------------- single scratch arena (aliased regions, disjoint lifetimes) ----
// qbuf   [BH][NTOK][HD]   : written by QKV gemm, read by pool(q); then DEAD
// obuf   aliases qbuf     : written by flash, read by proj gemm
// kbuf   [BH][NTOK][HD]   : written by QKV gemm, read by pool(k); then DEAD
// relh/relw alias kbuf    : written by rel_k, read by flash
// vbuf   [BH][NTOK][HD]   : written by QKV gemm, read by pool(v); then DEAD
// Rh/Rw  alias vbuf       : written by rtab_k, read by rel_k
// qp/kp/vp                : pooled+LN tensors
#define OFF_QBUF 0L
#define OFF_OBUF 0L
#define OFF_KBUF 9636864L
#define OFF_RELH 9636864L
#define OFF_RELW 12446720L
#define OFF_VBUF 19273728L
#define OFF_RH   19273728L
#define OFF_RW   19424256L
#define OFF_QP   28910592L
#define OFF_KP   38547456L
#define OFF_VP   40958976L
#define ARENA_SZ 43370496L
__device__ float g_arena[ARENA_SZ];   // ~173 MB

// ---------------- 128x128x16 fp32 GEMM (QKV scatter / output projection) -------
// MODE 0: C = x @ w_qkv + b_qkv, scattered to q/k/v head-major arena regions
// MODE 3: out = obuf @ w_proj + b_proj -> d_out
template<int MODE>
__global__ void __launch_bounds__(256) gemm_k(const float* __restrict__ Aext,
                                             const float* __restrict__ Bext,
                                             const float* __restrict__ bias,
                                             float* __restrict__ outext,
                                             int M, int N, int K, int lda, int ldb)
{
    __shared__ __align__(16) float As[16][128];
    __shared__ __align__(16) float Bs[16][128];

    const float* A  = (MODE == 0) ? Aext : (g_arena + OFF_OBUF);
    const float* Bm = Bext;

    const int row0 = blockIdx.y * 128;
    const int col0 = blockIdx.x * 128;
    const int tid  = threadIdx.x;
    const int tx   = tid & 15;
    const int ty   = tid >> 4;

    float acc[8][8];
    #pragma unroll
    for (int i = 0; i < 8; i++)
        #pragma unroll
        for (int j = 0; j < 8; j++) acc[i][j] = 0.0f;

    const int numKT = (K + 15) >> 4;
    for (int kt = 0; kt < numKT; kt++) {
        const int k0 = kt << 4;
        #pragma unroll
        for (int i = 0; i < 8; i++) {
            int idx = tid + i * 256;
            int m = idx >> 4, k = idx & 15;
            int gm = row0 + m, gk = k0 + k;
            As[k][m] = (gm < M && gk < K) ? A[(long)gm * lda + gk] : 0.0f;
        }
        #pragma unroll
        for (int i = 0; i < 8; i++) {
            int idx = tid + i * 256;
            int k = idx >> 7, n = idx & 127;
            int gk = k0 + k, gn = col0 + n;
            Bs[k][n] = (gk < K && gn < N) ? Bm[(long)gk * ldb + gn] : 0.0f;
        }
        __syncthreads();

        #pragma unroll
        for (int kk = 0; kk < 16; kk++) {
            float4 a0 = *(const float4*)&As[kk][ty * 8];
            float4 a1 = *(const float4*)&As[kk][ty * 8 + 4];
            float4 b0 = *(const float4*)&Bs[kk][tx * 8];
            float4 b1 = *(const float4*)&Bs[kk][tx * 8 + 4];
            float a[8] = {a0.x, a0.y, a0.z, a0.w, a1.x, a1.y, a1.z, a1.w};
            float b[8] = {b0.x, b0.y, b0.z, b0.w, b1.x, b1.y, b1.z, b1.w};
            #pragma unroll
            for (int i = 0; i < 8; i++)
                #pragma unroll
                for (int j = 0; j < 8; j++)
                    acc[i][j] = fmaf(a[i], b[j], acc[i][j]);
        }
        __syncthreads();
    }

    #pragma unroll
    for (int i = 0; i < 8; i++) {
        int gm = row0 + ty * 8 + i;
        if (gm >= M) continue;
        #pragma unroll
        for (int j = 0; j < 8; j++) {
            int gn = col0 + tx * 8 + j;
            if (gn >= N) continue;
            float v = acc[i][j] + bias[gn];
            if (MODE == 0) {
                int b  = gm / NTOK, n = gm - b * NTOK;
                int m3 = gn / DMODEL;
                int rem = gn - m3 * DMODEL;
                int h = rem / HD, c = rem - h * HD;
                long off = (m3 == 0) ? OFF_QBUF : (m3 == 1) ? OFF_KBUF : OFF_VBUF;
                g_arena[off + (((long)(b * NH + h)) * NTOK + n) * HD + c] = v;
            } else {
                outext[(long)gm * DMODEL + gn] = v;
            }
        }
    }
}

// ---------------- fused depthwise 3x3 pool + LayerNorm ----------------
// grid: (outlen, BH), block: 96 threads (one channel each)
template<int SEL>   // 0=q(stride1), 1=k(stride2), 2=v(stride2)
__global__ void pool_ln_k(const float* __restrict__ wconv, const float* __restrict__ gamma,
                          const float* __restrict__ beta)
{
    const int stride = (SEL == 0) ? 1 : 2;
    const int ow     = (SEL == 0) ? HW : KHW;
    const int outlen = (SEL == 0) ? QLEN : KLEN;
    const float* in  = g_arena + ((SEL == 0) ? OFF_QBUF : (SEL == 1) ? OFF_KBUF : OFF_VBUF);
    float* out       = g_arena + ((SEL == 0) ? OFF_QP   : (SEL == 1) ? OFF_KP   : OFF_VP);

    const int t = blockIdx.x, z = blockIdx.y, c = threadIdx.x;
    const float* inz = in + (long)z * NTOK * HD;
    float val;
    if (t == 0) {
        val = inz[c];
    } else {
        int p = t - 1;
        int i = p / ow, j = p - i * ow;
        val = 0.0f;
        #pragma unroll
        for (int di = 0; di < 3; di++)
            #pragma unroll
            for (int dj = 0; dj < 3; dj++) {
                int r = i * stride + di - 1;
                int w = j * stride + dj - 1;
                if (r >= 0 && r < HW && w >= 0 && w < HW)
                    val = fmaf(inz[(1 + r * HW + w) * HD + c], wconv[(di * 3 + dj) * HD + c], val);
            }
    }
    __shared__ float red[96];
    red[c] = val; __syncthreads();
    if (c < 48) red[c] += red[c + 48]; __syncthreads();
    if (c < 24) red[c] += red[c + 24]; __syncthreads();
    if (c < 12) red[c] += red[c + 12]; __syncthreads();
    if (c < 6)  red[c] += red[c + 6];  __syncthreads();
    if (c == 0) red[0] = red[0] + red[1] + red[2] + red[3] + red[4] + red[5];
    __syncthreads();
    float mean = red[0] * (1.0f / 96.0f);
    __syncthreads();
    float d = val - mean;
    red[c] = d * d; __syncthreads();
    if (c < 48) red[c] += red[c + 48]; __syncthreads();
    if (c < 24) red[c] += red[c + 24]; __syncthreads();
    if (c < 12) red[c] += red[c + 12]; __syncthreads();
    if (c < 6)  red[c] += red[c + 6];  __syncthreads();
    if (c == 0) red[0] = red[0] + red[1] + red[2] + red[3] + red[4] + red[5];
    __syncthreads();
    float var = red[0] * (1.0f / 96.0f);
    out[((long)z * outlen + t) * HD + c] = d * rsqrtf(var + 1e-6f) * gamma[c] + beta[c];
}

// ---------------- rel-pos gathered tables Rh/Rw ----------------
__global__ void rtab_k(const float* __restrict__ rel_pos_h, const float* __restrict__ rel_pos_w)
{
    int idx = blockIdx.x * blockDim.x + threadIdx.x;
    if (idx >= HW * KHW * HD) return;
    int qh = idx / (KHW * HD);
    int r  = idx - qh * (KHW * HD);
    int kh = r / HD;
    int c  = r - kh * HD;
    int d  = qh - 2 * kh + 54;            // q_ratio=1, k_ratio=2, offset=(28-1)*2
    g_arena[OFF_RH + idx] = rel_pos_h[d * HD + c];
    g_arena[OFF_RW + idx] = rel_pos_w[d * HD + c];
}

// ---------------- rel_h / rel_w projections ----------------
// grid: (3136, BH), block 64: threads 0..27 -> rel_h, 32..59 -> rel_w
__global__ void rel_k()
{
    __shared__ float qv[96];
    const int qi = blockIdx.x, z = blockIdx.y;
    const int qh = qi / HW, qw = qi - qh * HW;
    for (int i = threadIdx.x; i < 96; i += 64)
        qv[i] = g_arena[OFF_QP + ((long)z * QLEN + 1 + qi) * HD + i];
    __syncthreads();
    int t = threadIdx.x;
    if (t < KHW) {
        const float* R = g_arena + OFF_RH + (qh * KHW + t) * HD;
        float s = 0.0f;
        #pragma unroll 8
        for (int c = 0; c < HD; c++) s = fmaf(qv[c], R[c], s);
        g_arena[OFF_RELH + ((long)z * 3136 + qi) * KHW + t] = s;
    } else if (t >= 32 && t < 32 + KHW) {
        int k = t - 32;
        const float* R = g_arena + OFF_RW + (qw * KHW + k) * HD;
        float s = 0.0f;
        #pragma unroll 8
        for (int c = 0; c < HD; c++) s = fmaf(qv[c], R[c], s);
        g_arena[OFF_RELW + ((long)z * 3136 + qi) * KHW + k] = s;
    }
}

// ---------------- fused flash attention: S=scale*QK^T+bias, softmax, O=PV+q ----
// grid (ceil(QLEN/64), BH), 256 threads. Thread (ty=tid/16, tx=tid%16):
//   rows {ty+16i}, score cols {tx+16j}, O cols {tx+16j, j<6}.
#define FBM 64
#define FBN 64
#define QS_OFF   0                       // Qs[96][65]
#define KS_OFF   (96*65)                 // Ks[96][65]
#define VS_OFF   (2*96*65)               // Vs[64][96]
#define PS_OFF   (2*96*65 + 64*96)       // Ps[64][65]
#define RHS_OFF  (PS_OFF + 64*65)        // RHs[64][28]
#define RWS_OFF  (RHS_OFF + 64*28)
#define FL_SMEM_FLOATS (RWS_OFF + 64*28) // 26368 floats = 105472 B
__global__ void __launch_bounds__(256) flash_k()
{
    extern __shared__ float sm[];
    const int z  = blockIdx.y;
    const int q0 = blockIdx.x * FBM;
    const int tid = threadIdx.x;
    const int tx = tid & 15, ty = tid >> 4;

    const float* qp = g_arena + OFF_QP + (long)z * QLEN * HD;
    const float* kp = g_arena + OFF_KP + (long)z * KLEN * HD;
    const float* vp = g_arena + OFF_VP + (long)z * KLEN * HD;

    // Q tile (transposed, padded) + rel-pos rows (invariant over key tiles)
    for (int idx = tid; idx < FBM * HD; idx += 256) {
        int row = idx / HD, c = idx - row * HD;
        int qi = q0 + row;
        sm[QS_OFF + c * 65 + row] = (qi < QLEN) ? qp[(long)qi * HD + c] : 0.0f;
    }
    for (int idx = tid; idx < FBM * KHW; idx += 256) {
        int row = idx / KHW, t = idx - row * KHW;
        int qi = q0 + row;
        float h = 0.0f, w = 0.0f;
        if (qi >= 1 && qi < QLEN) {
            long rb = ((long)z * 3136 + (qi - 1)) * KHW;
            h = g_arena[OFF_RELH + rb + t];
            w = g_arena[OFF_RELW + rb + t];
        }
        sm[RHS_OFF + row * KHW + t] = h;
        sm[RWS_OFF + row * KHW + t] = w;
    }

    float o[4][6];
    float m[4], l[4];
    #pragma unroll
    for (int i = 0; i < 4; i++) {
        m[i] = -1e30f; l[i] = 0.0f;
        #pragma unroll
        for (int j = 0; j < 6; j++) o[i][j] = 0.0f;
    }

    for (int kb = 0; kb < KLEN; kb += FBN) {
        // load K (transposed, padded) and V tiles
        for (int idx = tid; idx < FBN * HD; idx += 256) {
            int j = idx / HD, c = idx - j * HD;
            int ki = kb + j;
            float kv = 0.0f, vv = 0.0f;
            if (ki < KLEN) { kv = kp[(long)ki * HD + c]; vv = vp[(long)ki * HD + c]; }
            sm[KS_OFF + c * 65 + j] = kv;
            sm[VS_OFF + j * HD + c] = vv;
        }
        __syncthreads();

        // S = Q K^T
        float s[4][4];
        #pragma unroll
        for (int i = 0; i < 4; i++)
            #pragma unroll
            for (int j = 0; j < 4; j++) s[i][j] = 0.0f;
        #pragma unroll 4
        for (int c = 0; c < HD; c++) {
            float a0 = sm[QS_OFF + c * 65 + ty];
            float a1 = sm[QS_OFF + c * 65 + ty + 16];
            float a2 = sm[QS_OFF + c * 65 + ty + 32];
            float a3 = sm[QS_OFF + c * 65 + ty + 48];
            float b0 = sm[KS_OFF + c * 65 + tx];
            float b1 = sm[KS_OFF + c * 65 + tx + 16];
            float b2 = sm[KS_OFF + c * 65 + tx + 32];
            float b3 = sm[KS_OFF + c * 65 + tx + 48];
            float a[4] = {a0, a1, a2, a3}, b[4] = {b0, b1, b2, b3};
            #pragma unroll
            for (int i = 0; i < 4; i++)
                #pragma unroll
                for (int j = 0; j < 4; j++)
                    s[i][j] = fmaf(a[i], b[j], s[i][j]);
        }

        // scale + rel-pos bias + key mask
        #pragma unroll
        for (int i = 0; i < 4; i++) {
            int row = ty + 16 * i;
            int qi = q0 + row;
            #pragma unroll
            for (int j = 0; j < 4; j++) {
                int ki = kb + tx + 16 * j;
                float v = s[i][j] * SCALE_F;
                if (ki < KLEN) {
                    if (qi > 0 && ki > 0 && qi < QLEN) {
                        int kk = ki - 1;
                        int kh = kk / KHW, kw = kk - kh * KHW;
                        v += sm[RHS_OFF + row * KHW + kh] + sm[RWS_OFF + row * KHW + kw];
                    }
                } else v = -1e30f;
                s[i][j] = v;
            }
        }

        // online softmax update (row reduction across the 16 tx lanes)
        #pragma unroll
        for (int i = 0; i < 4; i++) {
            float mx = fmaxf(fmaxf(s[i][0], s[i][1]), fmaxf(s[i][2], s[i][3]));
            #pragma unroll
            for (int off = 8; off > 0; off >>= 1)
                mx = fmaxf(mx, __shfl_xor_sync(0xffffffffu, mx, off));
            float nm = fmaxf(m[i], mx);
            float corr = expf(m[i] - nm);
            float rs = 0.0f;
            #pragma unroll
            for (int j = 0; j < 4; j++) { s[i][j] = expf(s[i][j] - nm); rs += s[i][j]; }
            #pragma unroll
            for (int off = 8; off > 0; off >>= 1)
                rs += __shfl_xor_sync(0xffffffffu, rs, off);
            l[i] = l[i] * corr + rs;
            m[i] = nm;
            #pragma unroll
            for (int j = 0; j < 6; j++) o[i][j] *= corr;
            int row = ty + 16 * i;
            #pragma unroll
            for (int j = 0; j < 4; j++)
                sm[PS_OFF + row * 65 + tx + 16 * j] = s[i][j];
        }
        __syncthreads();

        // O += P V
        #pragma unroll 4
        for (int k = 0; k < FBN; k++) {
            float p0 = sm[PS_OFF + (ty)      * 65 + k];
            float p1 = sm[PS_OFF + (ty + 16) * 65 + k];
            float p2 = sm[PS_OFF + (ty + 32) * 65 + k];
            float p3 = sm[PS_OFF + (ty + 48) * 65 + k];
            float p[4] = {p0, p1, p2, p3};
            #pragma unroll
            for (int j = 0; j < 6; j++) {
                float vv = sm[VS_OFF + k * HD + tx + 16 * j];
                #pragma unroll
                for (int i = 0; i < 4; i++)
                    o[i][j] = fmaf(p[i], vv, o[i][j]);
            }
        }
        __syncthreads();
    }

    // epilogue: normalize, residual, head-transposed write to obuf
    const int b = z >> 3, h = z & 7;
    #pragma unroll
    for (int i = 0; i < 4; i++) {
        int qi = q0 + ty + 16 * i;
        if (qi >= QLEN) continue;
        float inv = 1.0f / l[i];
        #pragma unroll
        for (int j = 0; j < 6; j++) {
            int c = tx + 16 * j;
            float v = o[i][j] * inv + qp[(long)qi * HD + c];
            g_arena[OFF_OBUF + ((long)(b * NTOK + qi)) * DMODEL + h * HD + c] = v;
        }
    }
}

// ---------------- launcher (kernel launches ONLY — graph-capturable) ----------------
extern "C" void kernel_launch(void* const* d_in, const int* in_sizes, int n_in,
                              void* d_out, int out_size)
{
    (void)in_sizes; (void)n_in; (void)out_size;
    const float* x         = (const float*)d_in[0];
    const float* w_qkv     = (const float*)d_in[1];
    const float* b_qkv     = (const float*)d_in[2];
    const float* conv_q    = (const float*)d_in[3];
    const float* conv_k    = (const float*)d_in[4];
    const float* conv_v    = (const float*)d_in[5];
    const float* gq        = (const float*)d_in[6];
    const float* bq        = (const float*)d_in[7];
    const float* gk        = (const float*)d_in[8];
    const float* bk        = (const float*)d_in[9];
    const float* gv        = (const float*)d_in[10];
    const float* bv        = (const float*)d_in[11];
    const float* rel_pos_h = (const float*)d_in[12];
    const float* rel_pos_w = (const float*)d_in[13];
    const float* w_proj    = (const float*)d_in[14];
    const float* b_proj    = (const float*)d_in[15];
    float* out = (float*)d_out;

    static bool attr_set = false;
    if (!attr_set) {
        cudaFuncSetAttribute(flash_k, cudaFuncAttributeMaxDynamicSharedMemorySize,
                             FL_SMEM_FLOATS * (int)sizeof(float));
        attr_set = true;
    }

    // 1) QKV GEMM + scatter into head-major q/k/v
    {
        dim3 grid((2304 + 127) / 128, (MROWS + 127) / 128, 1);
        gemm_k<0><<<grid, 256>>>(x, w_qkv, b_qkv, nullptr,
                                 MROWS, 3 * DMODEL, DMODEL, DMODEL, 3 * DMODEL);
    }
    // 2) pooling + LN (q stride 1, k/v stride 2)
    pool_ln_k<0><<<dim3(QLEN, BH), 96>>>(conv_q, gq, bq);
    pool_ln_k<1><<<dim3(KLEN, BH), 96>>>(conv_k, gk, bk);
    pool_ln_k<2><<<dim3(KLEN, BH), 96>>>(conv_v, gv, bv);
    // 3) rel-pos tables + projections
    rtab_k<<<(HW * KHW * HD + 255) / 256, 256>>>(rel_pos_h, rel_pos_w);
    rel_k<<<dim3(HW * HW, BH), 64>>>();
    // 4) fused attention (scores + bias + softmax + PV + residual)
    flash_k<<<dim3((QLEN + FBM - 1) / FBM, BH), 256,
              FL_SMEM_FLOATS * (int)sizeof(float)>>>();
    // 5) projection
    {
        dim3 grid((DMODEL + 127) / 128, (MROWS + 127) / 128, 1);
        gemm_k<3><<<grid, 256>>>(nullptr, w_proj, b_proj, out,
                                 MROWS, DMODEL, DMODEL, DMODEL, DMODEL);
    }
}

// round 4
// speedup vs baseline: 1.4089x; 1.4089x over previous
#include <cuda_runtime.h>
#include <cuda_bf16.h>
#include <math.h>

// ---------------- problem constants ----------------
#define BDIM   4
#define NTOK   3137        // 1 + 56*56
#define DMODEL 768
#define NH     8
#define HD     96
#define HW     56
#define QLEN   3137
#define KHW    28
#define KLEN   785         // 1 + 28*28
#define BH     32          // BDIM*NH
#define MROWS  12548       // BDIM*NTOK
#define SCALE_F 0.10206207261596575f   // 96^-0.5

// ---------------- single scratch arena (aliased regions, disjoint lifetimes) ----
#define OFF_QBUF 0L
#define OFF_OBUF 0L
#define OFF_KBUF 9636864L
#define OFF_RELH 9636864L
#define OFF_RELW 12446720L
#define OFF_VBUF 19273728L
#define OFF_RH   19273728L
#define OFF_RW   19424256L
#define OFF_QP   28910592L
#define OFF_KP   38547456L
#define OFF_VP   40958976L
#define ARENA_SZ 43370496L
__device__ float g_arena[ARENA_SZ];   // ~173 MB

// ---------------- mma.sync helpers (bf16 split-precision fp32 GEMM) ------------
__device__ __forceinline__ void ldsm_x4(unsigned& r0, unsigned& r1, unsigned& r2, unsigned& r3,
                                        unsigned addr)
{
    asm volatile("ldmatrix.sync.aligned.m8n8.x4.shared.b16 {%0,%1,%2,%3}, [%4];"
                 : "=r"(r0), "=r"(r1), "=r"(r2), "=r"(r3) : "r"(addr));
}
__device__ __forceinline__ void ldsm_x2t(unsigned& r0, unsigned& r1, unsigned addr)
{
    asm volatile("ldmatrix.sync.aligned.m8n8.x2.trans.shared.b16 {%0,%1}, [%2];"
                 : "=r"(r0), "=r"(r1) : "r"(addr));
}
__device__ __forceinline__ void mma_bf16(float* d, const unsigned* a, const unsigned* b)
{
    asm volatile("mma.sync.aligned.m16n8k16.row.col.f32.bf16.bf16.f32 "
                 "{%0,%1,%2,%3}, {%4,%5,%6,%7}, {%8,%9}, {%0,%1,%2,%3};"
                 : "+f"(d[0]), "+f"(d[1]), "+f"(d[2]), "+f"(d[3])
                 : "r"(a[0]), "r"(a[1]), "r"(a[2]), "r"(a[3]), "r"(b[0]), "r"(b[1]));
}
__device__ __forceinline__ void split_bf16(float x, __nv_bfloat16& h, __nv_bfloat16& l)
{
    h = __float2bfloat16(x);
    l = __float2bfloat16(x - __bfloat162float(h));
}

// ---------------- 128x128x32 split-bf16 tensor-core GEMM -----------------------
// MODE 0: C = x @ w_qkv + b_qkv, scattered to q/k/v head-major arena regions
// MODE 3: out = obuf @ w_proj + b_proj -> d_out
// 256 threads = 8 warps (2 x 4); warp tile 64x32 = 4x4 m16n8 atoms.
#define APITCH 40    // bf16 pitch for A smem rows (conflict-free ldmatrix)
#define BPITCH 136   // bf16 pitch for B smem rows
template<int MODE>
__global__ void __launch_bounds__(256) gemm_mma(const float* __restrict__ Aext,
                                               const float* __restrict__ Bm,
                                               const float* __restrict__ bias,
                                               float* __restrict__ outext,
                                               int M, int N, int K, int lda, int ldb)
{
    __shared__ __align__(16) __nv_bfloat16 Ah[128 * APITCH];
    __shared__ __align__(16) __nv_bfloat16 Al[128 * APITCH];
    __shared__ __align__(16) __nv_bfloat16 Bh[32 * BPITCH];
    __shared__ __align__(16) __nv_bfloat16 Bl[32 * BPITCH];

    const float* A = (MODE == 0) ? Aext : (g_arena + OFF_OBUF);

    const int tid  = threadIdx.x;
    const int lane = tid & 31;
    const int warp = tid >> 5;
    const int wm   = (warp >> 2) * 64;   // warp m offset in tile
    const int wn   = (warp & 3) * 32;    // warp n offset in tile
    const int row0 = blockIdx.y * 128;
    const int col0 = blockIdx.x * 128;

    float acc[4][4][4];
    #pragma unroll
    for (int mi = 0; mi < 4; mi++)
        #pragma unroll
        for (int nj = 0; nj < 4; nj++)
            #pragma unroll
            for (int r = 0; r < 4; r++) acc[mi][nj][r] = 0.0f;

    const unsigned aHbase = (unsigned)__cvta_generic_to_shared(Ah);
    const unsigned aLbase = (unsigned)__cvta_generic_to_shared(Al);
    const unsigned bHbase = (unsigned)__cvta_generic_to_shared(Bh);
    const unsigned bLbase = (unsigned)__cvta_generic_to_shared(Bl);

    for (int k0 = 0; k0 < K; k0 += 32) {
        // ---- load A tile 128x32 fp32, split into hi/lo bf16 ----
        #pragma unroll
        for (int i = 0; i < 4; i++) {
            int r  = (tid >> 3) + i * 32;
            int c4 = (tid & 7) * 4;
            int gm = row0 + r;
            float4 v = make_float4(0.f, 0.f, 0.f, 0.f);
            if (gm < M) v = *(const float4*)&A[(long)gm * lda + k0 + c4];
            __nv_bfloat16 h0, h1, h2, h3, l0, l1, l2, l3;
            split_bf16(v.x, h0, l0); split_bf16(v.y, h1, l1);
            split_bf16(v.z, h2, l2); split_bf16(v.w, h3, l3);
            int o = r * APITCH + c4;
            *(__nv_bfloat162*)&Ah[o]     = __halves2bfloat162(h0, h1);
            *(__nv_bfloat162*)&Ah[o + 2] = __halves2bfloat162(h2, h3);
            *(__nv_bfloat162*)&Al[o]     = __halves2bfloat162(l0, l1);
            *(__nv_bfloat162*)&Al[o + 2] = __halves2bfloat162(l2, l3);
        }
        // ---- load B tile 32x128 fp32 (K and N are exact multiples) ----
        #pragma unroll
        for (int i = 0; i < 4; i++) {
            int r  = (tid >> 5) + i * 8;
            int c4 = lane * 4;
            float4 v = *(const float4*)&Bm[(long)(k0 + r) * ldb + col0 + c4];
            __nv_bfloat16 h0, h1, h2, h3, l0, l1, l2, l3;
            split_bf16(v.x, h0, l0); split_bf16(v.y, h1, l1);
            split_bf16(v.z, h2, l2); split_bf16(v.w, h3, l3);
            int o = r * BPITCH + c4;
            *(__nv_bfloat162*)&Bh[o]     = __halves2bfloat162(h0, h1);
            *(__nv_bfloat162*)&Bh[o + 2] = __halves2bfloat162(h2, h3);
            *(__nv_bfloat162*)&Bl[o]     = __halves2bfloat162(l0, l1);
            *(__nv_bfloat162*)&Bl[o + 2] = __halves2bfloat162(l2, l3);
        }
        __syncthreads();

        #pragma unroll
        for (int kk = 0; kk < 2; kk++) {
            const int ks = kk * 16;
            // A fragments for this k16 slice
            unsigned ah[4][4], al[4][4];
            const int arow = lane & 7;
            const int asel = lane >> 3;
            const unsigned aoff =
                (unsigned)(((wm + arow + (asel & 1) * 8) * APITCH + ks + (asel >> 1) * 8) * 2);
            #pragma unroll
            for (int mi = 0; mi < 4; mi++) {
                unsigned d = aoff + (unsigned)(mi * 16 * APITCH * 2);
                ldsm_x4(ah[mi][0], ah[mi][1], ah[mi][2], ah[mi][3], aHbase + d);
                ldsm_x4(al[mi][0], al[mi][1], al[mi][2], al[mi][3], aLbase + d);
            }
            // B fragments per n-atom, then 3 split MMAs against all m-atoms
            const int brow = lane & 7;
            const int bsel = (lane >> 3) & 1;
            #pragma unroll
            for (int nj = 0; nj < 4; nj++) {
                unsigned boff =
                    (unsigned)(((ks + bsel * 8 + brow) * BPITCH + wn + nj * 8) * 2);
                unsigned bh[2], bl[2];
                ldsm_x2t(bh[0], bh[1], bHbase + boff);
                ldsm_x2t(bl[0], bl[1], bLbase + boff);
                #pragma unroll
                for (int mi = 0; mi < 4; mi++) {
                    mma_bf16(acc[mi][nj], ah[mi], bh);   // hi*hi
                    mma_bf16(acc[mi][nj], al[mi], bh);   // lo*hi
                    mma_bf16(acc[mi][nj], ah[mi], bl);   // hi*lo
                }
            }
        }
        __syncthreads();
    }

    // ---- epilogue ----
    const int g = lane >> 2, t = lane & 3;
    #pragma unroll
    for (int mi = 0; mi < 4; mi++)
        #pragma unroll
        for (int nj = 0; nj < 4; nj++)
            #pragma unroll
            for (int r = 0; r < 4; r++) {
                int gm = row0 + wm + mi * 16 + g + (r >> 1) * 8;
                int gn = col0 + wn + nj * 8 + 2 * t + (r & 1);
                if (gm >= M) continue;
                float v = acc[mi][nj][r] + bias[gn];
                if (MODE == 0) {
                    int b  = gm / NTOK, n = gm - b * NTOK;
                    int m3 = gn / DMODEL;
                    int rem = gn - m3 * DMODEL;
                    int h = rem / HD, c = rem - h * HD;
                    long off = (m3 == 0) ? OFF_QBUF : (m3 == 1) ? OFF_KBUF : OFF_VBUF;
                    g_arena[off + (((long)(b * NH + h)) * NTOK + n) * HD + c] = v;
                } else {
                    outext[(long)gm * DMODEL + gn] = v;
                }
            }
}

// ---------------- fused depthwise 3x3 pool + LayerNorm ----------------
template<int SEL>   // 0=q(stride1), 1=k(stride2), 2=v(stride2)
__global__ void pool_ln_k(const float* __restrict__ wconv, const float* __restrict__ gamma,
                          const float* __restrict__ beta)
{
    const int stride = (SEL == 0) ? 1 : 2;
    const int ow     = (SEL == 0) ? HW : KHW;
    const int outlen = (SEL == 0) ? QLEN : KLEN;
    const float* in  = g_arena + ((SEL == 0) ? OFF_QBUF : (SEL == 1) ? OFF_KBUF : OFF_VBUF);
    float* out       = g_arena + ((SEL == 0) ? OFF_QP   : (SEL == 1) ? OFF_KP   : OFF_VP);

    const int t = blockIdx.x, z = blockIdx.y, c = threadIdx.x;
    const float* inz = in + (long)z * NTOK * HD;
    float val;
    if (t == 0) {
        val = inz[c];
    } else {
        int p = t - 1;
        int i = p / ow, j = p - i * ow;
        val = 0.0f;
        #pragma unroll
        for (int di = 0; di < 3; di++)
            #pragma unroll
            for (int dj = 0; dj < 3; dj++) {
                int r = i * stride + di - 1;
                int w = j * stride + dj - 1;
                if (r >= 0 && r < HW && w >= 0 && w < HW)
                    val = fmaf(inz[(1 + r * HW + w) * HD + c], wconv[(di * 3 + dj) * HD + c], val);
            }
    }
    __shared__ float red[96];
    red[c] = val; __syncthreads();
    if (c < 48) red[c] += red[c + 48]; __syncthreads();
    if (c < 24) red[c] += red[c + 24]; __syncthreads();
    if (c < 12) red[c] += red[c + 12]; __syncthreads();
    if (c < 6)  red[c] += red[c + 6];  __syncthreads();
    if (c == 0) red[0] = red[0] + red[1] + red[2] + red[3] + red[4] + red[5];
    __syncthreads();
    float mean = red[0] * (1.0f / 96.0f);
    __syncthreads();
    float d = val - mean;
    red[c] = d * d; __syncthreads();
    if (c < 48) red[c] += red[c + 48]; __syncthreads();
    if (c < 24) red[c] += red[c + 24]; __syncthreads();
    if (c < 12) red[c] += red[c + 12]; __syncthreads();
    if (c < 6)  red[c] += red[c + 6];  __syncthreads();
    if (c == 0) red[0] = red[0] + red[1] + red[2] + red[3] + red[4] + red[5];
    __syncthreads();
    float var = red[0] * (1.0f / 96.0f);
    out[((long)z * outlen + t) * HD + c] = d * rsqrtf(var + 1e-6f) * gamma[c] + beta[c];
}

// ---------------- rel-pos gathered tables Rh/Rw ----------------
__global__ void rtab_k(const float* __restrict__ rel_pos_h, const float* __restrict__ rel_pos_w)
{
    int idx = blockIdx.x * blockDim.x + threadIdx.x;
    if (idx >= HW * KHW * HD) return;
    int qh = idx / (KHW * HD);
    int r  = idx - qh * (KHW * HD);
    int kh = r / HD;
    int c  = r - kh * HD;
    int d  = qh - 2 * kh + 54;
    g_arena[OFF_RH + idx] = rel_pos_h[d * HD + c];
    g_arena[OFF_RW + idx] = rel_pos_w[d * HD + c];
}

// ---------------- rel_h / rel_w projections ----------------
__global__ void rel_k()
{
    __shared__ float qv[96];
    const int qi = blockIdx.x, z = blockIdx.y;
    const int qh = qi / HW, qw = qi - qh * HW;
    for (int i = threadIdx.x; i < 96; i += 64)
        qv[i] = g_arena[OFF_QP + ((long)z * QLEN + 1 + qi) * HD + i];
    __syncthreads();
    int t = threadIdx.x;
    if (t < KHW) {
        const float* R = g_arena + OFF_RH + (qh * KHW + t) * HD;
        float s = 0.0f;
        #pragma unroll 8
        for (int c = 0; c < HD; c++) s = fmaf(qv[c], R[c], s);
        g_arena[OFF_RELH + ((long)z * 3136 + qi) * KHW + t] = s;
    } else if (t >= 32 && t < 32 + KHW) {
        int k = t - 32;
        const float* R = g_arena + OFF_RW + (qw * KHW + k) * HD;
        float s = 0.0f;
        #pragma unroll 8
        for (int c = 0; c < HD; c++) s = fmaf(qv[c], R[c], s);
        g_arena[OFF_RELW + ((long)z * 3136 + qi) * KHW + k] = s;
    }
}

// ---------------- fused flash attention ----------------
#define FBM 64
#define FBN 64
#define QS_OFF   0                       // Qs[96][65]
#define KS_OFF   (96*65)                 // Ks[96][65]
#define VS_OFF   (2*96*65)               // Vs[64][96]
#define PS_OFF   (2*96*65 + 64*96)       // Ps[64][65]
#define RHS_OFF  (PS_OFF + 64*65)        // RHs[64][28]
#define RWS_OFF  (RHS_OFF + 64*28)
#define FL_SMEM_FLOATS (RWS_OFF + 64*28) // 26368 floats = 105472 B
__global__ void __launch_bounds__(256) flash_k()
{
    extern __shared__ float sm[];
    const int z  = blockIdx.y;
    const int q0 = blockIdx.x * FBM;
    const int tid = threadIdx.x;
    const int tx = tid & 15, ty = tid >> 4;

    const float* qp = g_arena + OFF_QP + (long)z * QLEN * HD;
    const float* kp = g_arena + OFF_KP + (long)z * KLEN * HD;
    const float* vp = g_arena + OFF_VP + (long)z * KLEN * HD;

    for (int idx = tid; idx < FBM * HD; idx += 256) {
        int row = idx / HD, c = idx - row * HD;
        int qi = q0 + row;
        sm[QS_OFF + c * 65 + row] = (qi < QLEN) ? qp[(long)qi * HD + c] : 0.0f;
    }
    for (int idx = tid; idx < FBM * KHW; idx += 256) {
        int row = idx / KHW, t = idx - row * KHW;
        int qi = q0 + row;
        float h = 0.0f, w = 0.0f;
        if (qi >= 1 && qi < QLEN) {
            long rb = ((long)z * 3136 + (qi - 1)) * KHW;
            h = g_arena[OFF_RELH + rb + t];
            w = g_arena[OFF_RELW + rb + t];
        }
        sm[RHS_OFF + row * KHW + t] = h;
        sm[RWS_OFF + row * KHW + t] = w;
    }

    float o[4][6];
    float m[4], l[4];
    #pragma unroll
    for (int i = 0; i < 4; i++) {
        m[i] = -1e30f; l[i] = 0.0f;
        #pragma unroll
        for (int j = 0; j < 6; j++) o[i][j] = 0.0f;
    }

    for (int kb = 0; kb < KLEN; kb += FBN) {
        for (int idx = tid; idx < FBN * HD; idx += 256) {
            int j = idx / HD, c = idx - j * HD;
            int ki = kb + j;
            float kv = 0.0f, vv = 0.0f;
            if (ki < KLEN) { kv = kp[(long)ki * HD + c]; vv = vp[(long)ki * HD + c]; }
            sm[KS_OFF + c * 65 + j] = kv;
            sm[VS_OFF + j * HD + c] = vv;
        }
        __syncthreads();

        float s[4][4];
        #pragma unroll
        for (int i = 0; i < 4; i++)
            #pragma unroll
            for (int j = 0; j < 4; j++) s[i][j] = 0.0f;
        #pragma unroll 4
        for (int c = 0; c < HD; c++) {
            float a0 = sm[QS_OFF + c * 65 + ty];
            float a1 = sm[QS_OFF + c * 65 + ty + 16];
            float a2 = sm[QS_OFF + c * 65 + ty + 32];
            float a3 = sm[QS_OFF + c * 65 + ty + 48];
            float b0 = sm[KS_OFF + c * 65 + tx];
            float b1 = sm[KS_OFF + c * 65 + tx + 16];
            float b2 = sm[KS_OFF + c * 65 + tx + 32];
            float b3 = sm[KS_OFF + c * 65 + tx + 48];
            float a[4] = {a0, a1, a2, a3}, b[4] = {b0, b1, b2, b3};
            #pragma unroll
            for (int i = 0; i < 4; i++)
                #pragma unroll
                for (int j = 0; j < 4; j++)
                    s[i][j] = fmaf(a[i], b[j], s[i][j]);
        }

        #pragma unroll
        for (int i = 0; i < 4; i++) {
            int row = ty + 16 * i;
            int qi = q0 + row;
            #pragma unroll
            for (int j = 0; j < 4; j++) {
                int ki = kb + tx + 16 * j;
                float v = s[i][j] * SCALE_F;
                if (ki < KLEN) {
                    if (qi > 0 && ki > 0 && qi < QLEN) {
                        int kk = ki - 1;
                        int kh = kk / KHW, kw = kk - kh * KHW;
                        v += sm[RHS_OFF + row * KHW + kh] + sm[RWS_OFF + row * KHW + kw];
                    }
                } else v = -1e30f;
                s[i][j] = v;
            }
        }

        #pragma unroll
        for (int i = 0; i < 4; i++) {
            float mx = fmaxf(fmaxf(s[i][0], s[i][1]), fmaxf(s[i][2], s[i][3]));
            #pragma unroll
            for (int off = 8; off > 0; off >>= 1)
                mx = fmaxf(mx, __shfl_xor_sync(0xffffffffu, mx, off));
            float nm = fmaxf(m[i], mx);
            float corr = __expf(m[i] - nm);
            float rs = 0.0f;
            #pragma unroll
            for (int j = 0; j < 4; j++) { s[i][j] = __expf(s[i][j] - nm); rs += s[i][j]; }
            #pragma unroll
            for (int off = 8; off > 0; off >>= 1)
                rs += __shfl_xor_sync(0xffffffffu, rs, off);
            l[i] = l[i] * corr + rs;
            m[i] = nm;
            #pragma unroll
            for (int j = 0; j < 6; j++) o[i][j] *= corr;
            int row = ty + 16 * i;
            #pragma unroll
            for (int j = 0; j < 4; j++)
                sm[PS_OFF + row * 65 + tx + 16 * j] = s[i][j];
        }
        __syncthreads();

        #pragma unroll 4
        for (int k = 0; k < FBN; k++) {
            float p0 = sm[PS_OFF + (ty)      * 65 + k];
            float p1 = sm[PS_OFF + (ty + 16) * 65 + k];
            float p2 = sm[PS_OFF + (ty + 32) * 65 + k];
            float p3 = sm[PS_OFF + (ty + 48) * 65 + k];
            float p[4] = {p0, p1, p2, p3};
            #pragma unroll
            for (int j = 0; j < 6; j++) {
                float vv = sm[VS_OFF + k * HD + tx + 16 * j];
                #pragma unroll
                for (int i = 0; i < 4; i++)
                    o[i][j] = fmaf(p[i], vv, o[i][j]);
            }
        }
        __syncthreads();
    }

    const int b = z >> 3, h = z & 7;
    #pragma unroll
    for (int i = 0; i < 4; i++) {
        int qi = q0 + ty + 16 * i;
        if (qi >= QLEN) continue;
        float inv = 1.0f / l[i];
        #pragma unroll
        for (int j = 0; j < 6; j++) {
            int c = tx + 16 * j;
            float v = o[i][j] * inv + qp[(long)qi * HD + c];
            g_arena[OFF_OBUF + ((long)(b * NTOK + qi)) * DMODEL + h * HD + c] = v;
        }
    }
}

// ---------------- launcher (kernel launches ONLY — graph-capturable) ----------------
extern "C" void kernel_launch(void* const* d_in, const int* in_sizes, int n_in,
                              void* d_out, int out_size)
{
    (void)in_sizes; (void)n_in; (void)out_size;
    const float* x         = (const float*)d_in[0];
    const float* w_qkv     = (const float*)d_in[1];
    const float* b_qkv     = (const float*)d_in[2];
    const float* conv_q    = (const float*)d_in[3];
    const float* conv_k    = (const float*)d_in[4];
    const float* conv_v    = (const float*)d_in[5];
    const float* gq        = (const float*)d_in[6];
    const float* bq        = (const float*)d_in[7];
    const float* gk        = (const float*)d_in[8];
    const float* bk        = (const float*)d_in[9];
    const float* gv        = (const float*)d_in[10];
    const float* bv        = (const float*)d_in[11];
    const float* rel_pos_h = (const float*)d_in[12];
    const float* rel_pos_w = (const float*)d_in[13];
    const float* w_proj    = (const float*)d_in[14];
    const float* b_proj    = (const float*)d_in[15];
    float* out = (float*)d_out;

    static bool attr_set = false;
    if (!attr_set) {
        cudaFuncSetAttribute(flash_k, cudaFuncAttributeMaxDynamicSharedMemorySize,
                             FL_SMEM_FLOATS * (int)sizeof(float));
        attr_set = true;
    }

    // 1) QKV GEMM (split-bf16 tensor cores) + scatter into head-major q/k/v
    {
        dim3 grid(2304 / 128, (MROWS + 127) / 128, 1);
        gemm_mma<0><<<grid, 256>>>(x, w_qkv, b_qkv, nullptr,
                                   MROWS, 3 * DMODEL, DMODEL, DMODEL, 3 * DMODEL);
    }
    // 2) pooling + LN
    pool_ln_k<0><<<dim3(QLEN, BH), 96>>>(conv_q, gq, bq);
    pool_ln_k<1><<<dim3(KLEN, BH), 96>>>(conv_k, gk, bk);
    pool_ln_k<2><<<dim3(KLEN, BH), 96>>>(conv_v, gv, bv);
    // 3) rel-pos tables + projections
    rtab_k<<<(HW * KHW * HD + 255) / 256, 256>>>(rel_pos_h, rel_pos_w);
    rel_k<<<dim3(HW * HW, BH), 64>>>();
    // 4) fused attention
    flash_k<<<dim3((QLEN + FBM - 1) / FBM, BH), 256,
              FL_SMEM_FLOATS * (int)sizeof(float)>>>();
    // 5) projection (split-bf16 tensor cores)
    {
        dim3 grid(DMODEL / 128, (MROWS + 127) / 128, 1);
        gemm_mma<3><<<grid, 256>>>(nullptr, w_proj, b_proj, out,
                                   MROWS, DMODEL, DMODEL, DMODEL, DMODEL);
    }
}

// round 5
// speedup vs baseline: 1.6087x; 1.1418x over previous
#include <cuda_runtime.h>
#include <cuda_bf16.h>
#include <math.h>

// ---------------- problem constants ----------------
#define BDIM   4
#define NTOK   3137        // 1 + 56*56
#define DMODEL 768
#define NH     8
#define HD     96
#define HW     56
#define QLEN   3137
#define KHW    28
#define KLEN   785         // 1 + 28*28
#define BH     32          // BDIM*NH
#define MROWS  12548       // BDIM*NTOK
#define SCALE_F 0.10206207261596575f   // 96^-0.5

// ---------------- single scratch arena (aliased regions, disjoint lifetimes) ----
#define OFF_QBUF 0L
#define OFF_OBUF 0L
#define OFF_KBUF 9636864L
#define OFF_RELH 9636864L
#define OFF_RELW 12446720L
#define OFF_VBUF 19273728L
#define OFF_RH   19273728L
#define OFF_RW   19424256L
#define OFF_QP   28910592L
#define OFF_KP   38547456L
#define OFF_VP   40958976L
#define ARENA_SZ 43370496L
__device__ float g_arena[ARENA_SZ];   // ~173 MB

// ---------------- mma.sync helpers ----------------
__device__ __forceinline__ void ldsm_x4(unsigned& r0, unsigned& r1, unsigned& r2, unsigned& r3,
                                        unsigned addr)
{
    asm volatile("ldmatrix.sync.aligned.m8n8.x4.shared.b16 {%0,%1,%2,%3}, [%4];"
                 : "=r"(r0), "=r"(r1), "=r"(r2), "=r"(r3) : "r"(addr));
}
__device__ __forceinline__ void ldsm_x4t(unsigned& r0, unsigned& r1, unsigned& r2, unsigned& r3,
                                         unsigned addr)
{
    asm volatile("ldmatrix.sync.aligned.m8n8.x4.trans.shared.b16 {%0,%1,%2,%3}, [%4];"
                 : "=r"(r0), "=r"(r1), "=r"(r2), "=r"(r3) : "r"(addr));
}
__device__ __forceinline__ void ldsm_x2t(unsigned& r0, unsigned& r1, unsigned addr)
{
    asm volatile("ldmatrix.sync.aligned.m8n8.x2.trans.shared.b16 {%0,%1}, [%2];"
                 : "=r"(r0), "=r"(r1) : "r"(addr));
}
__device__ __forceinline__ void mma_bf16(float* d, const unsigned* a, const unsigned* b)
{
    asm volatile("mma.sync.aligned.m16n8k16.row.col.f32.bf16.bf16.f32 "
                 "{%0,%1,%2,%3}, {%4,%5,%6,%7}, {%8,%9}, {%0,%1,%2,%3};"
                 : "+f"(d[0]), "+f"(d[1]), "+f"(d[2]), "+f"(d[3])
                 : "r"(a[0]), "r"(a[1]), "r"(a[2]), "r"(a[3]), "r"(b[0]), "r"(b[1]));
}
__device__ __forceinline__ void split_bf16(float x, __nv_bfloat16& h, __nv_bfloat16& l)
{
    h = __float2bfloat16(x);
    l = __float2bfloat16(x - __bfloat162float(h));
}
__device__ __forceinline__ unsigned pack2(__nv_bfloat16 a, __nv_bfloat16 b)
{
    __nv_bfloat162 t = __halves2bfloat162(a, b);
    return *(unsigned*)&t;
}

// ---------------- 128x128x32 split-bf16 tensor-core GEMM -----------------------
#define APITCH 40
#define BPITCH 136
template<int MODE>   // 0: QKV scatter, 3: projection
__global__ void __launch_bounds__(256) gemm_mma(const float* __restrict__ Aext,
                                               const float* __restrict__ Bm,
                                               const float* __restrict__ bias,
                                               float* __restrict__ outext,
                                               int M, int N, int K, int lda, int ldb)
{
    __shared__ __align__(16) __nv_bfloat16 Ah[128 * APITCH];
    __shared__ __align__(16) __nv_bfloat16 Al[128 * APITCH];
    __shared__ __align__(16) __nv_bfloat16 Bh[32 * BPITCH];
    __shared__ __align__(16) __nv_bfloat16 Bl[32 * BPITCH];

    const float* A = (MODE == 0) ? Aext : (g_arena + OFF_OBUF);

    const int tid  = threadIdx.x;
    const int lane = tid & 31;
    const int warp = tid >> 5;
    const int wm   = (warp >> 2) * 64;
    const int wn   = (warp & 3) * 32;
    const int row0 = blockIdx.y * 128;
    const int col0 = blockIdx.x * 128;

    float acc[4][4][4];
    #pragma unroll
    for (int mi = 0; mi < 4; mi++)
        #pragma unroll
        for (int nj = 0; nj < 4; nj++)
            #pragma unroll
            for (int r = 0; r < 4; r++) acc[mi][nj][r] = 0.0f;

    const unsigned aHbase = (unsigned)__cvta_generic_to_shared(Ah);
    const unsigned aLbase = (unsigned)__cvta_generic_to_shared(Al);
    const unsigned bHbase = (unsigned)__cvta_generic_to_shared(Bh);
    const unsigned bLbase = (unsigned)__cvta_generic_to_shared(Bl);

    for (int k0 = 0; k0 < K; k0 += 32) {
        #pragma unroll
        for (int i = 0; i < 4; i++) {
            int r  = (tid >> 3) + i * 32;
            int c4 = (tid & 7) * 4;
            int gm = row0 + r;
            float4 v = make_float4(0.f, 0.f, 0.f, 0.f);
            if (gm < M) v = *(const float4*)&A[(long)gm * lda + k0 + c4];
            __nv_bfloat16 h0, h1, h2, h3, l0, l1, l2, l3;
            split_bf16(v.x, h0, l0); split_bf16(v.y, h1, l1);
            split_bf16(v.z, h2, l2); split_bf16(v.w, h3, l3);
            int o = r * APITCH + c4;
            *(__nv_bfloat162*)&Ah[o]     = __halves2bfloat162(h0, h1);
            *(__nv_bfloat162*)&Ah[o + 2] = __halves2bfloat162(h2, h3);
            *(__nv_bfloat162*)&Al[o]     = __halves2bfloat162(l0, l1);
            *(__nv_bfloat162*)&Al[o + 2] = __halves2bfloat162(l2, l3);
        }
        #pragma unroll
        for (int i = 0; i < 4; i++) {
            int r  = (tid >> 5) + i * 8;
            int c4 = lane * 4;
            float4 v = *(const float4*)&Bm[(long)(k0 + r) * ldb + col0 + c4];
            __nv_bfloat16 h0, h1, h2, h3, l0, l1, l2, l3;
            split_bf16(v.x, h0, l0); split_bf16(v.y, h1, l1);
            split_bf16(v.z, h2, l2); split_bf16(v.w, h3, l3);
            int o = r * BPITCH + c4;
            *(__nv_bfloat162*)&Bh[o]     = __halves2bfloat162(h0, h1);
            *(__nv_bfloat162*)&Bh[o + 2] = __halves2bfloat162(h2, h3);
            *(__nv_bfloat162*)&Bl[o]     = __halves2bfloat162(l0, l1);
            *(__nv_bfloat162*)&Bl[o + 2] = __halves2bfloat162(l2, l3);
        }
        __syncthreads();

        #pragma unroll
        for (int kk = 0; kk < 2; kk++) {
            const int ks = kk * 16;
            unsigned ah[4][4], al[4][4];
            const unsigned aoff =
                (unsigned)(((wm + (lane & 15)) * APITCH + ks + (lane >> 4) * 8) * 2);
            #pragma unroll
            for (int mi = 0; mi < 4; mi++) {
                unsigned d = aoff + (unsigned)(mi * 16 * APITCH * 2);
                ldsm_x4(ah[mi][0], ah[mi][1], ah[mi][2], ah[mi][3], aHbase + d);
                ldsm_x4(al[mi][0], al[mi][1], al[mi][2], al[mi][3], aLbase + d);
            }
            const int brow = lane & 7;
            const int bsel = (lane >> 3) & 1;
            #pragma unroll
            for (int nj = 0; nj < 4; nj++) {
                unsigned boff =
                    (unsigned)(((ks + bsel * 8 + brow) * BPITCH + wn + nj * 8) * 2);
                unsigned bh[2], bl[2];
                ldsm_x2t(bh[0], bh[1], bHbase + boff);
                ldsm_x2t(bl[0], bl[1], bLbase + boff);
                #pragma unroll
                for (int mi = 0; mi < 4; mi++) {
                    mma_bf16(acc[mi][nj], ah[mi], bh);
                    mma_bf16(acc[mi][nj], al[mi], bh);
                    mma_bf16(acc[mi][nj], ah[mi], bl);
                }
            }
        }
        __syncthreads();
    }

    const int g = lane >> 2, t = lane & 3;
    #pragma unroll
    for (int mi = 0; mi < 4; mi++)
        #pragma unroll
        for (int nj = 0; nj < 4; nj++)
            #pragma unroll
            for (int r = 0; r < 4; r++) {
                int gm = row0 + wm + mi * 16 + g + (r >> 1) * 8;
                int gn = col0 + wn + nj * 8 + 2 * t + (r & 1);
                if (gm >= M) continue;
                float v = acc[mi][nj][r] + bias[gn];
                if (MODE == 0) {
                    int b  = gm / NTOK, n = gm - b * NTOK;
                    int m3 = gn / DMODEL;
                    int rem = gn - m3 * DMODEL;
                    int h = rem / HD, c = rem - h * HD;
                    long off = (m3 == 0) ? OFF_QBUF : (m3 == 1) ? OFF_KBUF : OFF_VBUF;
                    g_arena[off + (((long)(b * NH + h)) * NTOK + n) * HD + c] = v;
                } else {
                    outext[(long)gm * DMODEL + gn] = v;
                }
            }
}

// ---------------- fused depthwise 3x3 pool + LayerNorm ----------------
template<int SEL>
__global__ void pool_ln_k(const float* __restrict__ wconv, const float* __restrict__ gamma,
                          const float* __restrict__ beta)
{
    const int stride = (SEL == 0) ? 1 : 2;
    const int ow     = (SEL == 0) ? HW : KHW;
    const int outlen = (SEL == 0) ? QLEN : KLEN;
    const float* in  = g_arena + ((SEL == 0) ? OFF_QBUF : (SEL == 1) ? OFF_KBUF : OFF_VBUF);
    float* out       = g_arena + ((SEL == 0) ? OFF_QP   : (SEL == 1) ? OFF_KP   : OFF_VP);

    const int t = blockIdx.x, z = blockIdx.y, c = threadIdx.x;
    const float* inz = in + (long)z * NTOK * HD;
    float val;
    if (t == 0) {
        val = inz[c];
    } else {
        int p = t - 1;
        int i = p / ow, j = p - i * ow;
        val = 0.0f;
        #pragma unroll
        for (int di = 0; di < 3; di++)
            #pragma unroll
            for (int dj = 0; dj < 3; dj++) {
                int r = i * stride + di - 1;
                int w = j * stride + dj - 1;
                if (r >= 0 && r < HW && w >= 0 && w < HW)
                    val = fmaf(inz[(1 + r * HW + w) * HD + c], wconv[(di * 3 + dj) * HD + c], val);
            }
    }
    __shared__ float red[96];
    red[c] = val; __syncthreads();
    if (c < 48) red[c] += red[c + 48]; __syncthreads();
    if (c < 24) red[c] += red[c + 24]; __syncthreads();
    if (c < 12) red[c] += red[c + 12]; __syncthreads();
    if (c < 6)  red[c] += red[c + 6];  __syncthreads();
    if (c == 0) red[0] = red[0] + red[1] + red[2] + red[3] + red[4] + red[5];
    __syncthreads();
    float mean = red[0] * (1.0f / 96.0f);
    __syncthreads();
    float d = val - mean;
    red[c] = d * d; __syncthreads();
    if (c < 48) red[c] += red[c + 48]; __syncthreads();
    if (c < 24) red[c] += red[c + 24]; __syncthreads();
    if (c < 12) red[c] += red[c + 12]; __syncthreads();
    if (c < 6)  red[c] += red[c + 6];  __syncthreads();
    if (c == 0) red[0] = red[0] + red[1] + red[2] + red[3] + red[4] + red[5];
    __syncthreads();
    float var = red[0] * (1.0f / 96.0f);
    out[((long)z * outlen + t) * HD + c] = d * rsqrtf(var + 1e-6f) * gamma[c] + beta[c];
}

// ---------------- rel-pos gathered tables Rh/Rw ----------------
__global__ void rtab_k(const float* __restrict__ rel_pos_h, const float* __restrict__ rel_pos_w)
{
    int idx = blockIdx.x * blockDim.x + threadIdx.x;
    if (idx >= HW * KHW * HD) return;
    int qh = idx / (KHW * HD);
    int r  = idx - qh * (KHW * HD);
    int kh = r / HD;
    int c  = r - kh * HD;
    int d  = qh - 2 * kh + 54;
    g_arena[OFF_RH + idx] = rel_pos_h[d * HD + c];
    g_arena[OFF_RW + idx] = rel_pos_w[d * HD + c];
}

// ---------------- rel_h / rel_w projections ----------------
__global__ void rel_k()
{
    __shared__ float qv[96];
    const int qi = blockIdx.x, z = blockIdx.y;
    const int qh = qi / HW, qw = qi - qh * HW;
    for (int i = threadIdx.x; i < 96; i += 64)
        qv[i] = g_arena[OFF_QP + ((long)z * QLEN + 1 + qi) * HD + i];
    __syncthreads();
    int t = threadIdx.x;
    if (t < KHW) {
        const float* R = g_arena + OFF_RH + (qh * KHW + t) * HD;
        float s = 0.0f;
        #pragma unroll 8
        for (int c = 0; c < HD; c++) s = fmaf(qv[c], R[c], s);
        g_arena[OFF_RELH + ((long)z * 3136 + qi) * KHW + t] = s;
    } else if (t >= 32 && t < 32 + KHW) {
        int k = t - 32;
        const float* R = g_arena + OFF_RW + (qw * KHW + k) * HD;
        float s = 0.0f;
        #pragma unroll 8
        for (int c = 0; c < HD; c++) s = fmaf(qv[c], R[c], s);
        g_arena[OFF_RELW + ((long)z * 3136 + qi) * KHW + k] = s;
    }
}

// ---------------- tensor-core flash attention ----------------
// Tile: 128 q-rows x 64 keys. 8 warps, warp w owns rows [16w, 16w+16).
// S = (Q*scale) K^T via split-bf16 MMA; online softmax in registers;
// P repacked from S accumulators into A-fragments; O += P V via split MMA.
#define FPITCH 104                       // bf16 pitch (96 cols + 8 pad)
#define SQH 0
#define SQL 26624
#define SKH 53248
#define SKL 66560
#define SVH 79872
#define SVL 93184
#define SRH 106496
#define SRW 120832
#define FL_SMEM_BYTES 135168
__global__ void __launch_bounds__(256) flash_k()
{
    extern __shared__ __align__(16) char smc[];
    __nv_bfloat16* Qh = (__nv_bfloat16*)(smc + SQH);
    __nv_bfloat16* Ql = (__nv_bfloat16*)(smc + SQL);
    __nv_bfloat16* Kh = (__nv_bfloat16*)(smc + SKH);
    __nv_bfloat16* Kl = (__nv_bfloat16*)(smc + SKL);
    __nv_bfloat16* Vh = (__nv_bfloat16*)(smc + SVH);
    __nv_bfloat16* Vl = (__nv_bfloat16*)(smc + SVL);
    float* RHs = (float*)(smc + SRH);
    float* RWs = (float*)(smc + SRW);

    const int z   = blockIdx.y;
    const int q0  = blockIdx.x * 128;
    const int tid = threadIdx.x;
    const int lane = tid & 31;
    const int warp = tid >> 5;
    const int wm   = warp * 16;
    const int g    = lane >> 2;
    const int t4   = lane & 3;

    const float* qp = g_arena + OFF_QP + (long)z * QLEN * HD;
    const float* kp = g_arena + OFF_KP + (long)z * KLEN * HD;
    const float* vp = g_arena + OFF_VP + (long)z * KLEN * HD;

    const unsigned qHb = (unsigned)__cvta_generic_to_shared(Qh);
    const unsigned qLb = (unsigned)__cvta_generic_to_shared(Ql);
    const unsigned kHb = (unsigned)__cvta_generic_to_shared(Kh);
    const unsigned kLb = (unsigned)__cvta_generic_to_shared(Kl);
    const unsigned vHb = (unsigned)__cvta_generic_to_shared(Vh);
    const unsigned vLb = (unsigned)__cvta_generic_to_shared(Vl);

    // ---- load Q (scale folded) + rel-pos bias rows ----
    for (int idx = tid; idx < 128 * 24; idx += 256) {
        int row = idx / 24, c4 = (idx - row * 24) * 4;
        int qi = q0 + row;
        float4 v = make_float4(0.f, 0.f, 0.f, 0.f);
        if (qi < QLEN) v = *(const float4*)&qp[(long)qi * HD + c4];
        v.x *= SCALE_F; v.y *= SCALE_F; v.z *= SCALE_F; v.w *= SCALE_F;
        __nv_bfloat16 h0, h1, h2, h3, l0, l1, l2, l3;
        split_bf16(v.x, h0, l0); split_bf16(v.y, h1, l1);
        split_bf16(v.z, h2, l2); split_bf16(v.w, h3, l3);
        int o = row * FPITCH + c4;
        *(__nv_bfloat162*)&Qh[o]     = __halves2bfloat162(h0, h1);
        *(__nv_bfloat162*)&Qh[o + 2] = __halves2bfloat162(h2, h3);
        *(__nv_bfloat162*)&Ql[o]     = __halves2bfloat162(l0, l1);
        *(__nv_bfloat162*)&Ql[o + 2] = __halves2bfloat162(l2, l3);
    }
    for (int idx = tid; idx < 128 * KHW; idx += 256) {
        int row = idx / KHW, tt = idx - row * KHW;
        int qi = q0 + row;
        float h = 0.0f, w = 0.0f;
        if (qi >= 1 && qi < QLEN) {
            long rb = ((long)z * 3136 + (qi - 1)) * KHW;
            h = g_arena[OFF_RELH + rb + tt];
            w = g_arena[OFF_RELW + rb + tt];
        }
        RHs[row * KHW + tt] = h;
        RWs[row * KHW + tt] = w;
    }

    float oc[12][4];
    #pragma unroll
    for (int nj = 0; nj < 12; nj++)
        #pragma unroll
        for (int r = 0; r < 4; r++) oc[nj][r] = 0.0f;
    float m0 = -1e30f, m1 = -1e30f, l0s = 0.0f, l1s = 0.0f;

    for (int kb = 0; kb < KLEN; kb += 64) {
        // ---- load K/V tile (split hi/lo) ----
        for (int idx = tid; idx < 64 * 24; idx += 256) {
            int row = idx / 24, c4 = (idx - row * 24) * 4;
            int ki = kb + row;
            float4 kv = make_float4(0.f, 0.f, 0.f, 0.f);
            float4 vv = make_float4(0.f, 0.f, 0.f, 0.f);
            if (ki < KLEN) {
                kv = *(const float4*)&kp[(long)ki * HD + c4];
                vv = *(const float4*)&vp[(long)ki * HD + c4];
            }
            int o = row * FPITCH + c4;
            __nv_bfloat16 h0, h1, h2, h3, l0, l1, l2, l3;
            split_bf16(kv.x, h0, l0); split_bf16(kv.y, h1, l1);
            split_bf16(kv.z, h2, l2); split_bf16(kv.w, h3, l3);
            *(__nv_bfloat162*)&Kh[o]     = __halves2bfloat162(h0, h1);
            *(__nv_bfloat162*)&Kh[o + 2] = __halves2bfloat162(h2, h3);
            *(__nv_bfloat162*)&Kl[o]     = __halves2bfloat162(l0, l1);
            *(__nv_bfloat162*)&Kl[o + 2] = __halves2bfloat162(l2, l3);
            split_bf16(vv.x, h0, l0); split_bf16(vv.y, h1, l1);
            split_bf16(vv.z, h2, l2); split_bf16(vv.w, h3, l3);
            *(__nv_bfloat162*)&Vh[o]     = __halves2bfloat162(h0, h1);
            *(__nv_bfloat162*)&Vh[o + 2] = __halves2bfloat162(h2, h3);
            *(__nv_bfloat162*)&Vl[o]     = __halves2bfloat162(l0, l1);
            *(__nv_bfloat162*)&Vl[o + 2] = __halves2bfloat162(l2, l3);
        }
        __syncthreads();

        // ---- S = Q K^T (8 n-atoms x 6 k16-slices x 3 split MMAs) ----
        float sc[8][4];
        #pragma unroll
        for (int nj = 0; nj < 8; nj++)
            #pragma unroll
            for (int r = 0; r < 4; r++) sc[nj][r] = 0.0f;

        #pragma unroll
        for (int ks6 = 0; ks6 < 6; ks6++) {
            const int ks = ks6 * 16;
            unsigned ah[4], al[4];
            unsigned qoff = (unsigned)(((wm + (lane & 15)) * FPITCH + ks + (lane >> 4) * 8) * 2);
            ldsm_x4(ah[0], ah[1], ah[2], ah[3], qHb + qoff);
            ldsm_x4(al[0], al[1], al[2], al[3], qLb + qoff);
            #pragma unroll
            for (int nj = 0; nj < 8; nj += 2) {
                // non-trans x4 on K[key][feat]: r0,r1 = atom nj k-halves; r2,r3 = atom nj+1
                unsigned koff = (unsigned)(((nj * 8 + (lane >> 4) * 8 + (lane & 7)) * FPITCH
                                            + ks + ((lane >> 3) & 1) * 8) * 2);
                unsigned bh[4], bl[4];
                ldsm_x4(bh[0], bh[1], bh[2], bh[3], kHb + koff);
                ldsm_x4(bl[0], bl[1], bl[2], bl[3], kLb + koff);
                mma_bf16(sc[nj],     ah, bh);
                mma_bf16(sc[nj],     al, bh);
                mma_bf16(sc[nj],     ah, bl);
                mma_bf16(sc[nj + 1], ah, bh + 2);
                mma_bf16(sc[nj + 1], al, bh + 2);
                mma_bf16(sc[nj + 1], ah, bl + 2);
            }
        }

        // ---- bias + mask ----
        const int r0loc = wm + g, r1loc = wm + g + 8;
        const int qi0 = q0 + r0loc, qi1 = q0 + r1loc;
        #pragma unroll
        for (int nj = 0; nj < 8; nj++) {
            #pragma unroll
            for (int r = 0; r < 4; r++) {
                int ki = kb + nj * 8 + 2 * t4 + (r & 1);
                int qi = (r < 2) ? qi0 : qi1;
                int rl = (r < 2) ? r0loc : r1loc;
                float v = sc[nj][r];
                if (ki < KLEN) {
                    if (qi > 0 && ki > 0 && qi < QLEN) {
                        int kk = ki - 1;
                        int kh = kk / KHW, kw = kk - kh * KHW;
                        v += RHs[rl * KHW + kh] + RWs[rl * KHW + kw];
                    }
                } else v = -1e30f;
                sc[nj][r] = v;
            }
        }

        // ---- online softmax (rows g, g+8; quad shuffle reduce) ----
        float mx0 = -1e30f, mx1 = -1e30f;
        #pragma unroll
        for (int nj = 0; nj < 8; nj++) {
            mx0 = fmaxf(mx0, fmaxf(sc[nj][0], sc[nj][1]));
            mx1 = fmaxf(mx1, fmaxf(sc[nj][2], sc[nj][3]));
        }
        #pragma unroll
        for (int off = 1; off <= 2; off <<= 1) {
            mx0 = fmaxf(mx0, __shfl_xor_sync(0xffffffffu, mx0, off));
            mx1 = fmaxf(mx1, __shfl_xor_sync(0xffffffffu, mx1, off));
        }
        float nm0 = fmaxf(m0, mx0), nm1 = fmaxf(m1, mx1);
        float corr0 = __expf(m0 - nm0), corr1 = __expf(m1 - nm1);
        m0 = nm0; m1 = nm1;
        float rs0 = 0.0f, rs1 = 0.0f;
        #pragma unroll
        for (int nj = 0; nj < 8; nj++) {
            sc[nj][0] = __expf(sc[nj][0] - nm0);
            sc[nj][1] = __expf(sc[nj][1] - nm0);
            sc[nj][2] = __expf(sc[nj][2] - nm1);
            sc[nj][3] = __expf(sc[nj][3] - nm1);
            rs0 += sc[nj][0] + sc[nj][1];
            rs1 += sc[nj][2] + sc[nj][3];
        }
        #pragma unroll
        for (int off = 1; off <= 2; off <<= 1) {
            rs0 += __shfl_xor_sync(0xffffffffu, rs0, off);
            rs1 += __shfl_xor_sync(0xffffffffu, rs1, off);
        }
        l0s = l0s * corr0 + rs0;
        l1s = l1s * corr1 + rs1;
        #pragma unroll
        for (int nj = 0; nj < 12; nj++) {
            oc[nj][0] *= corr0; oc[nj][1] *= corr0;
            oc[nj][2] *= corr1; oc[nj][3] *= corr1;
        }

        // ---- pack P into A-fragments (hi/lo), per k16 slice j ----
        unsigned pha[4][4], pla[4][4];
        #pragma unroll
        for (int j = 0; j < 4; j++) {
            float v0 = sc[2*j][0], v1 = sc[2*j][1], v2 = sc[2*j][2], v3 = sc[2*j][3];
            float v4 = sc[2*j+1][0], v5 = sc[2*j+1][1], v6 = sc[2*j+1][2], v7 = sc[2*j+1][3];
            __nv_bfloat16 h0,h1,h2,h3,h4,h5,h6,h7, e0,e1,e2,e3,e4,e5,e6,e7;
            split_bf16(v0,h0,e0); split_bf16(v1,h1,e1); split_bf16(v2,h2,e2); split_bf16(v3,h3,e3);
            split_bf16(v4,h4,e4); split_bf16(v5,h5,e5); split_bf16(v6,h6,e6); split_bf16(v7,h7,e7);
            pha[j][0] = pack2(h0, h1); pha[j][1] = pack2(h2, h3);
            pha[j][2] = pack2(h4, h5); pha[j][3] = pack2(h6, h7);
            pla[j][0] = pack2(e0, e1); pla[j][1] = pack2(e2, e3);
            pla[j][2] = pack2(e4, e5); pla[j][3] = pack2(e6, e7);
        }

        // ---- O += P V ----
        #pragma unroll
        for (int j = 0; j < 4; j++) {
            #pragma unroll
            for (int nj = 0; nj < 12; nj += 2) {
                unsigned voff = (unsigned)(((j * 16 + ((lane >> 3) & 1) * 8 + (lane & 7)) * FPITCH
                                            + (nj + (lane >> 4)) * 8) * 2);
                unsigned bh[4], bl[4];
                ldsm_x4t(bh[0], bh[1], bh[2], bh[3], vHb + voff);
                ldsm_x4t(bl[0], bl[1], bl[2], bl[3], vLb + voff);
                mma_bf16(oc[nj],     pha[j], bh);
                mma_bf16(oc[nj],     pla[j], bh);
                mma_bf16(oc[nj],     pha[j], bl);
                mma_bf16(oc[nj + 1], pha[j], bh + 2);
                mma_bf16(oc[nj + 1], pla[j], bh + 2);
                mma_bf16(oc[nj + 1], pha[j], bl + 2);
            }
        }
        __syncthreads();
    }

    // ---- epilogue: normalize, residual, head-transposed store ----
    const int b = z >> 3, h = z & 7;
    const int qi0 = q0 + wm + g, qi1 = q0 + wm + g + 8;
    float inv0 = 1.0f / l0s, inv1 = 1.0f / l1s;
    #pragma unroll
    for (int nj = 0; nj < 12; nj++) {
        int c = nj * 8 + 2 * t4;
        if (qi0 < QLEN) {
            float x0 = oc[nj][0] * inv0 + qp[(long)qi0 * HD + c];
            float x1 = oc[nj][1] * inv0 + qp[(long)qi0 * HD + c + 1];
            long o = OFF_OBUF + ((long)(b * NTOK + qi0)) * DMODEL + h * HD + c;
            g_arena[o] = x0; g_arena[o + 1] = x1;
        }
        if (qi1 < QLEN) {
            float x2 = oc[nj][2] * inv1 + qp[(long)qi1 * HD + c];
            float x3 = oc[nj][3] * inv1 + qp[(long)qi1 * HD + c + 1];
            long o = OFF_OBUF + ((long)(b * NTOK + qi1)) * DMODEL + h * HD + c;
            g_arena[o] = x2; g_arena[o + 1] = x3;
        }
    }
}

// ---------------- launcher (kernel launches ONLY — graph-capturable) ----------------
extern "C" void kernel_launch(void* const* d_in, const int* in_sizes, int n_in,
                              void* d_out, int out_size)
{
    (void)in_sizes; (void)n_in; (void)out_size;
    const float* x         = (const float*)d_in[0];
    const float* w_qkv     = (const float*)d_in[1];
    const float* b_qkv     = (const float*)d_in[2];
    const float* conv_q    = (const float*)d_in[3];
    const float* conv_k    = (const float*)d_in[4];
    const float* conv_v    = (const float*)d_in[5];
    const float* gq        = (const float*)d_in[6];
    const float* bq        = (const float*)d_in[7];
    const float* gk        = (const float*)d_in[8];
    const float* bk        = (const float*)d_in[9];
    const float* gv        = (const float*)d_in[10];
    const float* bv        = (const float*)d_in[11];
    const float* rel_pos_h = (const float*)d_in[12];
    const float* rel_pos_w = (const float*)d_in[13];
    const float* w_proj    = (const float*)d_in[14];
    const float* b_proj    = (const float*)d_in[15];
    float* out = (float*)d_out;

    static bool attr_set = false;
    if (!attr_set) {
        cudaFuncSetAttribute(flash_k, cudaFuncAttributeMaxDynamicSharedMemorySize,
                             FL_SMEM_BYTES);
        attr_set = true;
    }

    // 1) QKV GEMM (split-bf16 tensor cores) + scatter into head-major q/k/v
    {
        dim3 grid(2304 / 128, (MROWS + 127) / 128, 1);
        gemm_mma<0><<<grid, 256>>>(x, w_qkv, b_qkv, nullptr,
                                   MROWS, 3 * DMODEL, DMODEL, DMODEL, 3 * DMODEL);
    }
    // 2) pooling + LN
    pool_ln_k<0><<<dim3(QLEN, BH), 96>>>(conv_q, gq, bq);
    pool_ln_k<1><<<dim3(KLEN, BH), 96>>>(conv_k, gk, bk);
    pool_ln_k<2><<<dim3(KLEN, BH), 96>>>(conv_v, gv, bv);
    // 3) rel-pos tables + projections
    rtab_k<<<(HW * KHW * HD + 255) / 256, 256>>>(rel_pos_h, rel_pos_w);
    rel_k<<<dim3(HW * HW, BH), 64>>>();
    // 4) fused tensor-core flash attention
    flash_k<<<dim3((QLEN + 127) / 128, BH), 256, FL_SMEM_BYTES>>>();
    // 5) projection (split-bf16 tensor cores)
    {
        dim3 grid(DMODEL / 128, (MROWS + 127) / 128, 1);
        gemm_mma<3><<<grid, 256>>>(nullptr, w_proj, b_proj, out,
                                   MROWS, DMODEL, DMODEL, DMODEL, DMODEL);
    }
}